// round 4
// baseline (speedup 1.0000x reference)
#include <cuda_runtime.h>
#include <math.h>

#define DD 128
#define NNODE 64
#define NEDGE 1024
#define BATCH 512
#define NR (BATCH*NNODE)      // 32768 node rows
#define NRE (BATCH*NEDGE)     // 524288 edge rows
#define NSTEPS 5

// ---------------- scratch (device globals per harness rules) ----------------
__device__ float g_P[NR*DD];        // A @ edge0
__device__ float g_AC[NR*DD];       // a_cur (reused for t1)
__device__ float g_RP[NR*DD];       // r * prop
__device__ float g_Z[NR*DD];        // z
__device__ float g_prop[NR*DD];     // running prop state
__device__ float g_M[NSTEPS][DD*DD];   // (W_link^T)^k
__device__ float g_cv[NSTEPS][DD];     // bias chain c_k
__device__ float g_WrA[DD*DD], g_WrP[DD*DD];
__device__ float g_WzA[DD*DD], g_WzP[DD*DD];
__device__ float g_WhA[DD*DD], g_WhP[DD*DD];
__device__ float g_Wa1[DD*DD], g_Wo[DD*DD];
__device__ float g_rs[NR];          // rowsum of A per node-row
__device__ float g_att[BATCH*NNODE];
__device__ float g_resid[BATCH*DD];

// ---------------- tiny prep kernels ----------------
// Wt[i][o] = W[o][inOffset + i]  (transpose [out,in] -> [in][out])
__global__ void transpose_kernel(const float* __restrict__ W, float* __restrict__ Wt,
                                 int inStride, int inOffset) {
    Wt[threadIdx.x * DD + blockIdx.x] = W[blockIdx.x * inStride + inOffset + threadIdx.x];
}

// Mn[i][o] = sum_j Mp[i][j] * W[o][j]   (i.e. Mn = Mp @ W^T)
__global__ void matpow_kernel(const float* __restrict__ Mp, const float* __restrict__ W,
                              float* __restrict__ Mn) {
    int i = blockIdx.x, o = threadIdx.x;
    float s = 0.f;
    #pragma unroll 8
    for (int j = 0; j < DD; ++j) s += Mp[i*DD + j] * W[o*DD + j];
    Mn[i*DD + o] = s;
}

__global__ void cvec_init_kernel(const float* __restrict__ b, float* __restrict__ c0) {
    c0[threadIdx.x] = b[threadIdx.x];
}
// cnext[o] = sum_j cprev[j]*W[o][j] + b[o]
__global__ void cvec_step_kernel(const float* __restrict__ cprev, const float* __restrict__ W,
                                 const float* __restrict__ b, float* __restrict__ cnext) {
    int o = threadIdx.x;
    float s = b[o];
    #pragma unroll 8
    for (int j = 0; j < DD; ++j) s += cprev[j] * W[o*DD + j];
    cnext[o] = s;
}

// rs[row] = sum_e A[row][e]   (row = b*NNODE + n)
__global__ void rowsum_kernel(const float* __restrict__ A, float* __restrict__ rs) {
    int row = blockIdx.x;
    const float* a = A + (size_t)row * NEDGE;
    float s = 0.f;
    for (int i = threadIdx.x; i < NEDGE; i += 128) s += a[i];
    #pragma unroll
    for (int off = 16; off > 0; off >>= 1) s += __shfl_xor_sync(0xffffffffu, s, off);
    __shared__ float sh[4];
    if ((threadIdx.x & 31) == 0) sh[threadIdx.x >> 5] = s;
    __syncthreads();
    if (threadIdx.x == 0) rs[row] = sh[0] + sh[1] + sh[2] + sh[3];
}

// residual[b][d] = mean over (64 node rows + 1024 edge rows) of initial states
__global__ void residual_kernel(const float* __restrict__ prop0, const float* __restrict__ edge0,
                                float* __restrict__ resid) {
    int b = blockIdx.x, d = threadIdx.x;
    float s = 0.f;
    const float* p = prop0 + (size_t)b*NNODE*DD + d;
    #pragma unroll 8
    for (int n = 0; n < NNODE; ++n) s += p[(size_t)n*DD];
    const float* e = edge0 + (size_t)b*NEDGE*DD + d;
    #pragma unroll 8
    for (int n = 0; n < NEDGE; ++n) s += e[(size_t)n*DD];
    resid[b*DD + d] = s * (1.0f / (NNODE + NEDGE));
}

// ---------------- main tiled GEMM: C[r,128] = epilogue( X1@Ma (+ X2@Mb) ) ----------------
// Block tile: 64 rows x 128 cols, 256 threads (16x16), 4x8 register tile.
// M matrices are [in=128][out=128] row-major. Rows per grid.x block = 64.
// MODE 0: plain
// MODE 1: sigmoid(v + bias)                      (z gate)
// MODE 2: aux * sigmoid(v + bias)                (r * prop)
// MODE 3: (1-z)*aux + z*tanh(v + bias)           (prop update; zbuf, aux=prop)
// MODE 4: tanh(v + bias)                         (t1 / out)
// MODE 5: v + rs[r]*bias[c]                      (a_cur with b_link correction)
// MODE 6: v + bias[c]                            (edge_out with c5)
template<int MODE, bool DUAL>
__global__ void __launch_bounds__(256) gemm128(
    const float* __restrict__ X1, const float* __restrict__ Ma,
    const float* __restrict__ X2, const float* __restrict__ Mb,
    const float* __restrict__ bias,
    const float* __restrict__ aux,
    const float* __restrict__ zbuf,
    const float* __restrict__ rs,
    float* __restrict__ C)
{
    __shared__ __align__(16) float Ms[32][128];
    __shared__ float Xs[32][65];   // transposed: [k][row], pad 65 -> conflict-free

    const int tid = threadIdx.x;
    const int tx = tid & 15;       // col group: cols tx*8 .. tx*8+7
    const int ty = tid >> 4;       // row group: rows ty*4 .. ty*4+3
    const size_t rowBase = (size_t)blockIdx.x * 64;

    float acc[4][8];
    #pragma unroll
    for (int i = 0; i < 4; ++i)
        #pragma unroll
        for (int j = 0; j < 8; ++j) acc[i][j] = 0.f;

    const int ldk  = tid & 31;
    const int ldr0 = tid >> 5;

    #pragma unroll
    for (int pass = 0; pass < (DUAL ? 2 : 1); ++pass) {
        const float* X = pass ? X2 : X1;
        const float* M = pass ? Mb : Ma;
        #pragma unroll
        for (int k0 = 0; k0 < 128; k0 += 32) {
            // load 32x128 M tile (float4, fully coalesced)
            #pragma unroll
            for (int j = 0; j < 4; ++j) {
                int idx = tid + j*256;
                int kk = idx >> 5;
                int cc = (idx & 31) << 2;
                *reinterpret_cast<float4*>(&Ms[kk][cc]) =
                    *reinterpret_cast<const float4*>(&M[(k0 + kk)*128 + cc]);
            }
            // load 64x32 X tile, transposed into smem (coalesced gmem reads)
            #pragma unroll
            for (int j = 0; j < 8; ++j) {
                int r = ldr0 + j*8;
                Xs[ldk][r] = X[(rowBase + r)*128 + k0 + ldk];
            }
            __syncthreads();
            #pragma unroll
            for (int k = 0; k < 32; ++k) {
                float4 m0 = *reinterpret_cast<const float4*>(&Ms[k][tx*8]);
                float4 m1 = *reinterpret_cast<const float4*>(&Ms[k][tx*8 + 4]);
                float mc[8] = {m0.x, m0.y, m0.z, m0.w, m1.x, m1.y, m1.z, m1.w};
                #pragma unroll
                for (int i = 0; i < 4; ++i) {
                    float xv = Xs[k][ty*4 + i];
                    #pragma unroll
                    for (int j = 0; j < 8; ++j) acc[i][j] += xv * mc[j];
                }
            }
            __syncthreads();
        }
    }

    #pragma unroll
    for (int i = 0; i < 4; ++i) {
        size_t r = rowBase + ty*4 + i;
        #pragma unroll
        for (int j = 0; j < 8; ++j) {
            int c = tx*8 + j;
            size_t idx = r*128 + c;
            float v = acc[i][j];
            if (MODE == 0) {
                C[idx] = v;
            } else if (MODE == 1) {
                v += bias[c];
                C[idx] = 1.f / (1.f + expf(-v));
            } else if (MODE == 2) {
                v += bias[c];
                C[idx] = aux[idx] / (1.f + expf(-v));
            } else if (MODE == 3) {
                v += bias[c];
                float t  = tanhf(v);
                float zv = zbuf[idx];
                C[idx] = (1.f - zv) * aux[idx] + zv * t;
            } else if (MODE == 4) {
                C[idx] = tanhf(v + bias[c]);
            } else if (MODE == 5) {
                C[idx] = v + rs[r] * bias[c];
            } else { // MODE 6
                C[idx] = v + bias[c];
            }
        }
    }
}

// ---------------- batched P = A @ edge0 : per-batch [64,1024]x[1024,128] ----------------
__global__ void __launch_bounds__(256) bmm_P_kernel(const float* __restrict__ A,
                                                    const float* __restrict__ E,
                                                    float* __restrict__ P)
{
    __shared__ __align__(16) float Es[32][128];
    __shared__ float As[32][65];

    const int b = blockIdx.x;
    const float* Ab = A + (size_t)b * NNODE * NEDGE;
    const float* Eb = E + (size_t)b * NEDGE * DD;

    const int tid = threadIdx.x;
    const int tx = tid & 15;
    const int ty = tid >> 4;
    const int ldk  = tid & 31;
    const int ldr0 = tid >> 5;

    float acc[4][8];
    #pragma unroll
    for (int i = 0; i < 4; ++i)
        #pragma unroll
        for (int j = 0; j < 8; ++j) acc[i][j] = 0.f;

    for (int k0 = 0; k0 < NEDGE; k0 += 32) {
        #pragma unroll
        for (int j = 0; j < 4; ++j) {
            int idx = tid + j*256;
            int kk = idx >> 5;
            int cc = (idx & 31) << 2;
            *reinterpret_cast<float4*>(&Es[kk][cc]) =
                *reinterpret_cast<const float4*>(&Eb[(size_t)(k0 + kk)*128 + cc]);
        }
        #pragma unroll
        for (int j = 0; j < 8; ++j) {
            int r = ldr0 + j*8;
            As[ldk][r] = Ab[(size_t)r*NEDGE + k0 + ldk];
        }
        __syncthreads();
        #pragma unroll
        for (int k = 0; k < 32; ++k) {
            float4 m0 = *reinterpret_cast<const float4*>(&Es[k][tx*8]);
            float4 m1 = *reinterpret_cast<const float4*>(&Es[k][tx*8 + 4]);
            float mc[8] = {m0.x, m0.y, m0.z, m0.w, m1.x, m1.y, m1.z, m1.w};
            #pragma unroll
            for (int i = 0; i < 4; ++i) {
                float xv = As[k][ty*4 + i];
                #pragma unroll
                for (int j = 0; j < 8; ++j) acc[i][j] += xv * mc[j];
            }
        }
        __syncthreads();
    }
    float* Pb = P + (size_t)b * NNODE * DD;
    #pragma unroll
    for (int i = 0; i < 4; ++i)
        #pragma unroll
        for (int j = 0; j < 8; ++j)
            Pb[(ty*4 + i)*128 + tx*8 + j] = acc[i][j];
}

// ---------------- attention: atten dot + softmax over 64 nodes ----------------
__global__ void att_kernel(const float* __restrict__ T1, const float* __restrict__ W2,
                           const float* __restrict__ b2, float* __restrict__ att) {
    int b = blockIdx.x, n = threadIdx.x;   // 64 threads
    const float* t = T1 + ((size_t)b*NNODE + n)*DD;
    float s = b2[0];
    #pragma unroll 8
    for (int d = 0; d < DD; ++d) s += t[d] * W2[d];
    __shared__ float sv[NNODE];
    sv[n] = s;
    __syncthreads();
    float m = -1e30f;
    #pragma unroll 8
    for (int j = 0; j < NNODE; ++j) m = fmaxf(m, sv[j]);
    float e = expf(s - m);
    __shared__ float se[NNODE];
    se[n] = e;
    __syncthreads();
    float tot = 0.f;
    #pragma unroll 8
    for (int j = 0; j < NNODE; ++j) tot += se[j];
    att[b*NNODE + n] = e / tot;
}

// ---------------- final: res = relu(tanh(att·out) + residual) ----------------
__global__ void final_kernel(const float* __restrict__ att, const float* __restrict__ outbuf,
                             const float* __restrict__ resid, float* __restrict__ res) {
    int b = blockIdx.x, d = threadIdx.x;
    const float* a = att + b*NNODE;
    const float* o = outbuf + (size_t)b*NNODE*DD + d;
    float s = 0.f;
    #pragma unroll 8
    for (int n = 0; n < NNODE; ++n) s += a[n] * o[(size_t)n*DD];
    float v = tanhf(s) + resid[b*DD + d];
    res[b*DD + d] = fmaxf(v, 0.f);
}

// ---------------- launcher ----------------
extern "C" void kernel_launch(void* const* d_in, const int* in_sizes, int n_in,
                              void* d_out, int out_size) {
    const float* prop0  = (const float*)d_in[0];
    const float* edge0  = (const float*)d_in[1];
    const float* A      = (const float*)d_in[2];
    const float* W_link = (const float*)d_in[3];
    const float* b_link = (const float*)d_in[4];
    const float* W_r    = (const float*)d_in[5];
    const float* b_r    = (const float*)d_in[6];
    const float* W_z    = (const float*)d_in[7];
    const float* b_z    = (const float*)d_in[8];
    const float* W_h    = (const float*)d_in[9];
    const float* b_h    = (const float*)d_in[10];
    const float* W_att1 = (const float*)d_in[11];
    const float* b_att1 = (const float*)d_in[12];
    const float* W_att2 = (const float*)d_in[13];
    const float* b_att2 = (const float*)d_in[14];
    const float* W_out  = (const float*)d_in[15];
    const float* b_out  = (const float*)d_in[16];

    float* outp     = (float*)d_out;
    float* res_out  = outp;                                   // [B, D]
    float* out_out  = outp + (size_t)BATCH*DD;                // [B, N, D]
    float* edge_out = out_out + (size_t)BATCH*NNODE*DD;       // [B, E, D]

    float *pP, *pAC, *pRP, *pZ, *pProp, *pM, *pCv;
    float *pWrA, *pWrP, *pWzA, *pWzP, *pWhA, *pWhP, *pWa1, *pWo;
    float *pRs, *pAtt, *pResid;
    cudaGetSymbolAddress((void**)&pP, g_P);
    cudaGetSymbolAddress((void**)&pAC, g_AC);
    cudaGetSymbolAddress((void**)&pRP, g_RP);
    cudaGetSymbolAddress((void**)&pZ, g_Z);
    cudaGetSymbolAddress((void**)&pProp, g_prop);
    cudaGetSymbolAddress((void**)&pM, g_M);
    cudaGetSymbolAddress((void**)&pCv, g_cv);
    cudaGetSymbolAddress((void**)&pWrA, g_WrA);
    cudaGetSymbolAddress((void**)&pWrP, g_WrP);
    cudaGetSymbolAddress((void**)&pWzA, g_WzA);
    cudaGetSymbolAddress((void**)&pWzP, g_WzP);
    cudaGetSymbolAddress((void**)&pWhA, g_WhA);
    cudaGetSymbolAddress((void**)&pWhP, g_WhP);
    cudaGetSymbolAddress((void**)&pWa1, g_Wa1);
    cudaGetSymbolAddress((void**)&pWo, g_Wo);
    cudaGetSymbolAddress((void**)&pRs, g_rs);
    cudaGetSymbolAddress((void**)&pAtt, g_att);
    cudaGetSymbolAddress((void**)&pResid, g_resid);

    // --- weight prep: M_k = (W_link^T)^k, c_k bias chain, transposed gate weights
    transpose_kernel<<<DD, DD>>>(W_link, pM, DD, 0);                    // M_1
    for (int k = 1; k < NSTEPS; ++k)
        matpow_kernel<<<DD, DD>>>(pM + (k-1)*DD*DD, W_link, pM + k*DD*DD);
    cvec_init_kernel<<<1, DD>>>(b_link, pCv);                           // c_1 = b_link
    for (int k = 1; k < NSTEPS; ++k)
        cvec_step_kernel<<<1, DD>>>(pCv + (k-1)*DD, W_link, b_link, pCv + k*DD);
    transpose_kernel<<<DD, DD>>>(W_r, pWrA, 2*DD, 0);
    transpose_kernel<<<DD, DD>>>(W_r, pWrP, 2*DD, DD);
    transpose_kernel<<<DD, DD>>>(W_z, pWzA, 2*DD, 0);
    transpose_kernel<<<DD, DD>>>(W_z, pWzP, 2*DD, DD);
    transpose_kernel<<<DD, DD>>>(W_h, pWhA, 2*DD, 0);
    transpose_kernel<<<DD, DD>>>(W_h, pWhP, 2*DD, DD);
    transpose_kernel<<<DD, DD>>>(W_att1, pWa1, DD, 0);
    transpose_kernel<<<DD, DD>>>(W_out, pWo, DD, 0);

    // --- one-time heavy pieces
    rowsum_kernel<<<NR, 128>>>(A, pRs);
    bmm_P_kernel<<<BATCH, 256>>>(A, edge0, pP);                         // P = A @ edge0
    residual_kernel<<<BATCH, DD>>>(prop0, edge0, pResid);
    // final edge_states output: edge0 @ M_5 + c_5
    gemm128<6, false><<<NRE/64, 256>>>(edge0, pM + 4*DD*DD, nullptr, nullptr,
                                       pCv + 4*DD, nullptr, nullptr, nullptr, edge_out);

    // --- 5 GRU propagation steps
    const float* prop_cur = prop0;
    for (int s = 0; s < NSTEPS; ++s) {
        // a_cur = P @ M_{s+1} + rowsumA * c_{s+1}
        gemm128<5, false><<<NR/64, 256>>>(pP, pM + s*DD*DD, nullptr, nullptr,
                                          pCv + s*DD, nullptr, nullptr, pRs, pAC);
        // r*prop = sigmoid(a_cur@WrA + prop@WrP + b_r) * prop
        gemm128<2, true ><<<NR/64, 256>>>(pAC, pWrA, prop_cur, pWrP,
                                          b_r, prop_cur, nullptr, nullptr, pRP);
        // z = sigmoid(a_cur@WzA + prop@WzP + b_z)
        gemm128<1, true ><<<NR/64, 256>>>(pAC, pWzA, prop_cur, pWzP,
                                          b_z, nullptr, nullptr, nullptr, pZ);
        // prop = (1-z)*prop + z*tanh(a_cur@WhA + (r*prop)@WhP + b_h)
        gemm128<3, true ><<<NR/64, 256>>>(pAC, pWhA, pRP, pWhP,
                                          b_h, prop_cur, pZ, nullptr, pProp);
        prop_cur = pProp;
    }

    // --- readout
    gemm128<4, false><<<NR/64, 256>>>(pProp, pWa1, nullptr, nullptr,
                                      b_att1, nullptr, nullptr, nullptr, pAC);   // t1
    att_kernel<<<BATCH, NNODE>>>(pAC, W_att2, b_att2, pAtt);
    gemm128<4, false><<<NR/64, 256>>>(pProp, pWo, nullptr, nullptr,
                                      b_out, nullptr, nullptr, nullptr, out_out); // out
    final_kernel<<<BATCH, DD>>>(pAtt, out_out, pResid, res_out);                  // res
}

// round 7
// speedup vs baseline: 2.4420x; 2.4420x over previous
#include <cuda_runtime.h>
#include <cuda_bf16.h>
#include <math.h>
#include <stdint.h>

#define DD 128
#define NNODE 64
#define NEDGE 1024
#define BATCH 512
#define NR (BATCH*NNODE)      // 32768 node rows
#define NRE (BATCH*NEDGE)     // 524288 edge rows
#define NSTEPS 5
#define T128 (DD*DD)

// ---------------- scratch (device globals per harness rules) ----------------
__device__ __align__(16) __nv_bfloat16 g_Phi[NR*DD], g_Plo[NR*DD];
__device__ __align__(16) __nv_bfloat16 g_ph0[NR*DD], g_pl0[NR*DD];   // prop ping
__device__ __align__(16) __nv_bfloat16 g_ph1[NR*DD], g_pl1[NR*DD];   // prop pong
__device__ __align__(16) __nv_bfloat16 g_rph[NR*DD], g_rpl[NR*DD];   // r * prop
__device__ __align__(16) float g_Z[NR*DD];                           // z; reused for t1
__device__ __align__(16) __nv_bfloat16 g_Ehi[NRE*DD], g_Elo[NRE*DD]; // edge0 split
__device__ __align__(16) __nv_bfloat16 g_Ahi[BATCH*NNODE*NEDGE];     // A split
__device__ __align__(16) __nv_bfloat16 g_Alo[BATCH*NNODE*NEDGE];
__device__ __align__(16) float g_M[NSTEPS*T128];    // (W_link^T)^k, [j][k]
__device__ __align__(16) float g_MT[NSTEPS*T128];   // transpose, [k][j]
__device__ __align__(16) float g_cv[NSTEPS*DD];     // bias chain
__device__ __align__(16) __nv_bfloat16 g_Ghi[15*T128], g_Glo[15*T128]; // folded gate A-weights
__device__ __align__(16) __nv_bfloat16 g_WPhi[3*T128], g_WPlo[3*T128]; // gate P-part weights
__device__ __align__(16) float g_dv[15*DD];
__device__ __align__(16) __nv_bfloat16 g_Wa1hi[T128], g_Wa1lo[T128];
__device__ __align__(16) __nv_bfloat16 g_Wohi[T128],  g_Wolo[T128];
__device__ __align__(16) __nv_bfloat16 g_M5hi[T128],  g_M5lo[T128];
__device__ __align__(16) float g_rs[NR];
__device__ __align__(16) float g_att[BATCH*NNODE];
__device__ __align__(16) float g_resid[BATCH*DD];

// ---------------- helpers ----------------
__device__ __forceinline__ uint32_t smem_u32(const void* p) {
    return (uint32_t)__cvta_generic_to_shared(p);
}
__device__ __forceinline__ void ldm4(uint32_t* r, uint32_t addr) {
    asm volatile("ldmatrix.sync.aligned.m8n8.x4.shared.b16 {%0,%1,%2,%3}, [%4];"
        : "=r"(r[0]), "=r"(r[1]), "=r"(r[2]), "=r"(r[3]) : "r"(addr));
}
__device__ __forceinline__ void ldm4t(uint32_t* r, uint32_t addr) {
    asm volatile("ldmatrix.sync.aligned.m8n8.x4.trans.shared.b16 {%0,%1,%2,%3}, [%4];"
        : "=r"(r[0]), "=r"(r[1]), "=r"(r[2]), "=r"(r[3]) : "r"(addr));
}
__device__ __forceinline__ void mma16816(float* c, const uint32_t* a, uint32_t b0, uint32_t b1) {
    asm volatile("mma.sync.aligned.m16n8k16.row.col.f32.bf16.bf16.f32 "
        "{%0,%1,%2,%3}, {%4,%5,%6,%7}, {%8,%9}, {%0,%1,%2,%3};"
        : "+f"(c[0]), "+f"(c[1]), "+f"(c[2]), "+f"(c[3])
        : "r"(a[0]), "r"(a[1]), "r"(a[2]), "r"(a[3]), "r"(b0), "r"(b1));
}
__device__ __forceinline__ void split1(float v, __nv_bfloat16& h, __nv_bfloat16& l) {
    h = __float2bfloat16_rn(v);
    l = __float2bfloat16_rn(v - __bfloat162float(h));
}

// ---------------- tiny prep kernels ----------------
__global__ void transpose_kernel(const float* __restrict__ W, float* __restrict__ Wt,
                                 int inStride, int inOffset) {
    Wt[threadIdx.x * DD + blockIdx.x] = W[blockIdx.x * inStride + inOffset + threadIdx.x];
}

__global__ void matpow_kernel(const float* __restrict__ Mp, const float* __restrict__ W,
                              float* __restrict__ Mn) {
    int i = blockIdx.x, o = threadIdx.x;
    float s = 0.f;
    #pragma unroll 8
    for (int j = 0; j < DD; ++j) s += Mp[i*DD + j] * W[o*DD + j];
    Mn[i*DD + o] = s;
}

__global__ void cvec_init_kernel(const float* __restrict__ b, float* __restrict__ c0) {
    c0[threadIdx.x] = b[threadIdx.x];
}
__global__ void cvec_step_kernel(const float* __restrict__ cprev, const float* __restrict__ W,
                                 const float* __restrict__ b, float* __restrict__ cnext) {
    int o = threadIdx.x;
    float s = b[o];
    #pragma unroll 8
    for (int j = 0; j < DD; ++j) s += cprev[j] * W[o*DD + j];
    cnext[o] = s;
}

__global__ void rowsum_kernel(const float* __restrict__ A, float* __restrict__ rs) {
    int row = blockIdx.x;
    const float* a = A + (size_t)row * NEDGE;
    float s = 0.f;
    for (int i = threadIdx.x; i < NEDGE; i += 128) s += a[i];
    #pragma unroll
    for (int off = 16; off > 0; off >>= 1) s += __shfl_xor_sync(0xffffffffu, s, off);
    __shared__ float sh[4];
    if ((threadIdx.x & 31) == 0) sh[threadIdx.x >> 5] = s;
    __syncthreads();
    if (threadIdx.x == 0) rs[row] = sh[0] + sh[1] + sh[2] + sh[3];
}

__global__ void residual_kernel(const float* __restrict__ prop0, const float* __restrict__ edge0,
                                float* __restrict__ resid) {
    int b = blockIdx.x, d = threadIdx.x;
    float s = 0.f;
    const float* p = prop0 + (size_t)b*NNODE*DD + d;
    #pragma unroll 8
    for (int n = 0; n < NNODE; ++n) s += p[(size_t)n*DD];
    const float* e = edge0 + (size_t)b*NEDGE*DD + d;
    #pragma unroll 8
    for (int n = 0; n < NEDGE; ++n) s += e[(size_t)n*DD];
    resid[b*DD + d] = s * (1.0f / (NNODE + NEDGE));
}

// dv[combo][n] = sum_k c_s[k] * Wg[n][k]  (Wg stride 256, A-part)
__global__ void dvec_kernel(const float* __restrict__ W_r, const float* __restrict__ W_z,
                            const float* __restrict__ W_h, const float* __restrict__ cv,
                            float* __restrict__ dv) {
    int combo = blockIdx.x; int s = combo / 3, gate = combo % 3;
    const float* Wg = gate == 0 ? W_r : (gate == 1 ? W_z : W_h);
    const float* c  = cv + s*DD;
    int n = threadIdx.x;
    float sm = 0.f;
    #pragma unroll 8
    for (int k = 0; k < DD; ++k) sm += c[k] * Wg[n*2*DD + k];
    dv[combo*DD + n] = sm;
}

// split a 128x128 fp32 matrix view (rowStride, colOff) into bf16 hi/lo [n][k]
__global__ void split_mat_kernel(const float* __restrict__ src, int rowStride, int colOff,
                                 __nv_bfloat16* __restrict__ hi, __nv_bfloat16* __restrict__ lo) {
    int n = blockIdx.x, k = threadIdx.x;
    float v = src[n*rowStride + colOff + k];
    __nv_bfloat16 h, l; split1(v, h, l);
    hi[n*DD + k] = h; lo[n*DD + k] = l;
}

// big elementwise fp32 -> bf16 hi/lo split (float4 vectorized)
__global__ void split_big_kernel(const float* __restrict__ src, __nv_bfloat16* __restrict__ hi,
                                 __nv_bfloat16* __restrict__ lo, long n4) {
    long i = (long)blockIdx.x * blockDim.x + threadIdx.x;
    long stride = (long)gridDim.x * blockDim.x;
    for (; i < n4; i += stride) {
        float4 v = reinterpret_cast<const float4*>(src)[i];
        __nv_bfloat16 h0,l0,h1,l1,h2,l2,h3,l3;
        split1(v.x,h0,l0); split1(v.y,h1,l1); split1(v.z,h2,l2); split1(v.w,h3,l3);
        __nv_bfloat162 ha; ha.x=h0; ha.y=h1;
        __nv_bfloat162 hb; hb.x=h2; hb.y=h3;
        __nv_bfloat162 la; la.x=l0; la.y=l1;
        __nv_bfloat162 lb; lb.x=l2; lb.y=l3;
        reinterpret_cast<__nv_bfloat162*>(hi)[2*i]   = ha;
        reinterpret_cast<__nv_bfloat162*>(hi)[2*i+1] = hb;
        reinterpret_cast<__nv_bfloat162*>(lo)[2*i]   = la;
        reinterpret_cast<__nv_bfloat162*>(lo)[2*i+1] = lb;
    }
}

// G[combo][n][j] = sum_k Wg[n][k] * MT_s[k][j]   (fp32 tiled, split-bf16 output)
__global__ void __launch_bounds__(256) prep_G_kernel(
    const float* __restrict__ W_r, const float* __restrict__ W_z, const float* __restrict__ W_h,
    const float* __restrict__ MT, __nv_bfloat16* __restrict__ Ghi, __nv_bfloat16* __restrict__ Glo)
{
    __shared__ __align__(16) float Ms[32][128];
    __shared__ float Xs[32][65];
    int combo = blockIdx.y; int s = combo / 3, gate = combo % 3;
    const float* Wg = gate == 0 ? W_r : (gate == 1 ? W_z : W_h);
    const float* M  = MT + s*T128;
    const int tid = threadIdx.x;
    const int tx = tid & 15, ty = tid >> 4;
    const int rowBase = blockIdx.x * 64;
    const int ldk = tid & 31, ldr0 = tid >> 5;

    float acc[4][8];
    #pragma unroll
    for (int i = 0; i < 4; ++i)
        #pragma unroll
        for (int j = 0; j < 8; ++j) acc[i][j] = 0.f;

    for (int k0 = 0; k0 < 128; k0 += 32) {
        #pragma unroll
        for (int j = 0; j < 4; ++j) {
            int idx = tid + j*256;
            int kk = idx >> 5, cc = (idx & 31) << 2;
            *reinterpret_cast<float4*>(&Ms[kk][cc]) =
                *reinterpret_cast<const float4*>(&M[(k0 + kk)*128 + cc]);
        }
        #pragma unroll
        for (int j = 0; j < 8; ++j) {
            int r = ldr0 + j*8;
            Xs[ldk][r] = Wg[(rowBase + r)*2*DD + k0 + ldk];
        }
        __syncthreads();
        #pragma unroll
        for (int k = 0; k < 32; ++k) {
            float4 m0 = *reinterpret_cast<const float4*>(&Ms[k][tx*8]);
            float4 m1 = *reinterpret_cast<const float4*>(&Ms[k][tx*8 + 4]);
            float mc[8] = {m0.x,m0.y,m0.z,m0.w,m1.x,m1.y,m1.z,m1.w};
            #pragma unroll
            for (int i = 0; i < 4; ++i) {
                float xv = Xs[k][ty*4 + i];
                #pragma unroll
                for (int j = 0; j < 8; ++j) acc[i][j] += xv * mc[j];
            }
        }
        __syncthreads();
    }
    __nv_bfloat16* ghi = Ghi + combo*T128;
    __nv_bfloat16* glo = Glo + combo*T128;
    #pragma unroll
    for (int i = 0; i < 4; ++i) {
        int n = rowBase + ty*4 + i;
        #pragma unroll
        for (int j = 0; j < 8; ++j) {
            int c = tx*8 + j;
            __nv_bfloat16 h, l; split1(acc[i][j], h, l);
            ghi[n*DD + c] = h; glo[n*DD + c] = l;
        }
    }
}

// ---------------- tensor-core batched P = A @ E (split-bf16, K=1024) ----------------
// Per batch: [64,1024] @ [1024,128]. B operand (E) is [k][n]: use ldmatrix.trans.
__global__ void __launch_bounds__(256) bmm_tc_kernel(
    const __nv_bfloat16* __restrict__ Ahi, const __nv_bfloat16* __restrict__ Alo,
    const __nv_bfloat16* __restrict__ Ehi, const __nv_bfloat16* __restrict__ Elo,
    __nv_bfloat16* __restrict__ Phi, __nv_bfloat16* __restrict__ Plo)
{
    __shared__ __align__(16) __nv_bfloat16 Xs[64][72];
    __shared__ __align__(16) __nv_bfloat16 Ws[64][136];   // [k][n], 272B row = 16B-multiple
    const int b = blockIdx.x;
    const size_t abase = (size_t)b * NNODE * NEDGE;
    const size_t ebase = (size_t)b * NEDGE * DD;
    const int t = threadIdx.x;
    const int wid = t >> 5, lane = t & 31;
    const int wm = (wid & 1) * 32, wn = (wid >> 1) * 32;
    const int g = lane >> 2, tig = lane & 3;

    float acc[2][4][4];
    #pragma unroll
    for (int mt = 0; mt < 2; ++mt)
        #pragma unroll
        for (int nt = 0; nt < 4; ++nt)
            #pragma unroll
            for (int c = 0; c < 4; ++c) acc[mt][nt][c] = 0.f;

    #pragma unroll 1
    for (int term = 0; term < 3; ++term) {
        const __nv_bfloat16* Ab = (term == 2 ? Alo : Ahi) + abase;
        const __nv_bfloat16* Eb = (term == 1 ? Elo : Ehi) + ebase;
        for (int k0 = 0; k0 < NEDGE; k0 += 64) {
            __syncthreads();
            // A tile: 64 rows x 64 k
            #pragma unroll
            for (int j = 0; j < 2; ++j) {
                int u = t + j*256;
                int r = u >> 3, c = (u & 7) * 8;
                *reinterpret_cast<uint4*>(&Xs[r][c]) =
                    *reinterpret_cast<const uint4*>(Ab + (size_t)r*NEDGE + k0 + c);
            }
            // E tile: 64 k-rows x 128 n (natural layout)
            #pragma unroll
            for (int j = 0; j < 4; ++j) {
                int u = t + j*256;
                int r = u >> 4, c = (u & 15) * 8;
                *reinterpret_cast<uint4*>(&Ws[r][c]) =
                    *reinterpret_cast<const uint4*>(Eb + (size_t)(k0 + r)*DD + c);
            }
            __syncthreads();
            #pragma unroll
            for (int kk = 0; kk < 4; ++kk) {
                const int kl = kk * 16;
                uint32_t af[2][4];
                #pragma unroll
                for (int mt = 0; mt < 2; ++mt)
                    ldm4(af[mt], smem_u32(&Xs[wm + mt*16 + (lane & 15)][kl + (lane >> 4)*8]));
                #pragma unroll
                for (int q = 0; q < 2; ++q) {
                    uint32_t bf[4];
                    ldm4t(bf, smem_u32(&Ws[kl + ((lane >> 3) & 1)*8 + (lane & 7)]
                                          [wn + q*16 + (lane >> 4)*8]));
                    #pragma unroll
                    for (int mt = 0; mt < 2; ++mt) {
                        mma16816(acc[mt][2*q],     af[mt], bf[0], bf[1]);
                        mma16816(acc[mt][2*q + 1], af[mt], bf[2], bf[3]);
                    }
                }
            }
        }
    }
    #pragma unroll
    for (int mt = 0; mt < 2; ++mt)
        #pragma unroll
        for (int nt = 0; nt < 4; ++nt)
            #pragma unroll
            for (int h = 0; h < 2; ++h) {
                int row = wm + mt*16 + g + h*8;
                int col = wn + nt*8 + tig*2;
                size_t idx = (size_t)b * NNODE * DD + (size_t)row*DD + col;
                __nv_bfloat16 h0,l0,h1,l1;
                split1(acc[mt][nt][2*h],     h0, l0);
                split1(acc[mt][nt][2*h + 1], h1, l1);
                __nv_bfloat162 oh; oh.x=h0; oh.y=h1;
                __nv_bfloat162 ol; ol.x=l0; ol.y=l1;
                *reinterpret_cast<__nv_bfloat162*>(&Phi[idx]) = oh;
                *reinterpret_cast<__nv_bfloat162*>(&Plo[idx]) = ol;
            }
}

// ---------------- tensor-core GEMM: 128x128 block, up to 6 split terms ----------------
// MODE 0=R (write r*prop hi/lo), 1=Z (write z f32), 2=H (write new prop hi/lo),
// 3=T (tanh+bias f32), 4=E (plain+bias f32)
struct TCArgs {
    const __nv_bfloat16* xs[6];
    const __nv_bfloat16* ws[6];
    int nterms;
    const float* bias;
    const float* dvec;
    const float* rs;
    const __nv_bfloat16* p_hi;
    const __nv_bfloat16* p_lo;
    const float* zbuf;
    float* outf;
    __nv_bfloat16* out_hi;
    __nv_bfloat16* out_lo;
};

template<int MODE>
__global__ void __launch_bounds__(256) tc_gemm(TCArgs a) {
    __shared__ __align__(16) __nv_bfloat16 Xs[128][72];
    __shared__ __align__(16) __nv_bfloat16 Ws[128][72];
    const int t = threadIdx.x;
    const int wid = t >> 5, lane = t & 31;
    const int wm = (wid & 3) * 32, wn = (wid >> 2) * 64;
    const int g = lane >> 2, tig = lane & 3;
    const size_t rowBase = (size_t)blockIdx.x * 128;

    float acc[2][8][4];
    #pragma unroll
    for (int mt = 0; mt < 2; ++mt)
        #pragma unroll
        for (int nt = 0; nt < 8; ++nt)
            #pragma unroll
            for (int c = 0; c < 4; ++c) acc[mt][nt][c] = 0.f;

    const int lr = t >> 3;          // 0..31
    const int lc = (t & 7) * 8;

    #pragma unroll 1
    for (int term = 0; term < a.nterms; ++term) {
        const __nv_bfloat16* xb = a.xs[term] + rowBase * 128;
        const __nv_bfloat16* wb = a.ws[term];
        #pragma unroll
        for (int kc = 0; kc < 2; ++kc) {
            const int k0 = kc * 64;
            __syncthreads();
            #pragma unroll
            for (int i = 0; i < 4; ++i) {
                int r = lr + i*32;
                *reinterpret_cast<uint4*>(&Xs[r][lc]) =
                    *reinterpret_cast<const uint4*>(xb + (size_t)r*128 + k0 + lc);
                *reinterpret_cast<uint4*>(&Ws[r][lc]) =
                    *reinterpret_cast<const uint4*>(wb + (size_t)r*128 + k0 + lc);
            }
            __syncthreads();
            #pragma unroll
            for (int kk = 0; kk < 4; ++kk) {
                const int kl = kk * 16;
                uint32_t af[2][4];
                #pragma unroll
                for (int mt = 0; mt < 2; ++mt)
                    ldm4(af[mt], smem_u32(&Xs[wm + mt*16 + (lane & 15)][kl + (lane >> 4)*8]));
                #pragma unroll
                for (int q = 0; q < 4; ++q) {
                    uint32_t bf[4];
                    ldm4(bf, smem_u32(&Ws[wn + q*16 + (lane & 15)][kl + (lane >> 4)*8]));
                    #pragma unroll
                    for (int mt = 0; mt < 2; ++mt) {
                        mma16816(acc[mt][2*q],     af[mt], bf[0], bf[2]);
                        mma16816(acc[mt][2*q + 1], af[mt], bf[1], bf[3]);
                    }
                }
            }
        }
    }

    #pragma unroll
    for (int mt = 0; mt < 2; ++mt) {
        #pragma unroll
        for (int nt = 0; nt < 8; ++nt) {
            #pragma unroll
            for (int h = 0; h < 2; ++h) {
                size_t row = rowBase + wm + mt*16 + g + h*8;
                int col = wn + nt*8 + tig*2;
                float v0 = acc[mt][nt][2*h + 0];
                float v1 = acc[mt][nt][2*h + 1];
                size_t idx = row*128 + col;
                if (MODE == 3) {
                    float2 o; o.x = tanhf(v0 + a.bias[col]); o.y = tanhf(v1 + a.bias[col+1]);
                    *reinterpret_cast<float2*>(&a.outf[idx]) = o;
                } else if (MODE == 4) {
                    float2 o; o.x = v0 + a.bias[col]; o.y = v1 + a.bias[col+1];
                    *reinterpret_cast<float2*>(&a.outf[idx]) = o;
                } else {
                    float rsv = a.rs[row];
                    v0 += a.bias[col]   + rsv * a.dvec[col];
                    v1 += a.bias[col+1] + rsv * a.dvec[col+1];
                    if (MODE == 1) {
                        float2 o;
                        o.x = 1.f / (1.f + expf(-v0));
                        o.y = 1.f / (1.f + expf(-v1));
                        *reinterpret_cast<float2*>(&a.outf[idx]) = o;
                    } else if (MODE == 0) {
                        float r0 = 1.f / (1.f + expf(-v0));
                        float r1 = 1.f / (1.f + expf(-v1));
                        __nv_bfloat162 ph = *reinterpret_cast<const __nv_bfloat162*>(&a.p_hi[idx]);
                        __nv_bfloat162 pl = *reinterpret_cast<const __nv_bfloat162*>(&a.p_lo[idx]);
                        float p0 = __bfloat162float(ph.x) + __bfloat162float(pl.x);
                        float p1 = __bfloat162float(ph.y) + __bfloat162float(pl.y);
                        __nv_bfloat16 h0,l0,h1,l1;
                        split1(r0*p0, h0, l0); split1(r1*p1, h1, l1);
                        __nv_bfloat162 oh; oh.x=h0; oh.y=h1;
                        __nv_bfloat162 ol; ol.x=l0; ol.y=l1;
                        *reinterpret_cast<__nv_bfloat162*>(&a.out_hi[idx]) = oh;
                        *reinterpret_cast<__nv_bfloat162*>(&a.out_lo[idx]) = ol;
                    } else { // MODE 2 (H)
                        float h0v = tanhf(v0), h1v = tanhf(v1);
                        float2 z = *reinterpret_cast<const float2*>(&a.zbuf[idx]);
                        __nv_bfloat162 ph = *reinterpret_cast<const __nv_bfloat162*>(&a.p_hi[idx]);
                        __nv_bfloat162 pl = *reinterpret_cast<const __nv_bfloat162*>(&a.p_lo[idx]);
                        float p0 = __bfloat162float(ph.x) + __bfloat162float(pl.x);
                        float p1 = __bfloat162float(ph.y) + __bfloat162float(pl.y);
                        float pn0 = (1.f - z.x)*p0 + z.x*h0v;
                        float pn1 = (1.f - z.y)*p1 + z.y*h1v;
                        __nv_bfloat16 h0,l0,h1,l1;
                        split1(pn0, h0, l0); split1(pn1, h1, l1);
                        __nv_bfloat162 oh; oh.x=h0; oh.y=h1;
                        __nv_bfloat162 ol; ol.x=l0; ol.y=l1;
                        *reinterpret_cast<__nv_bfloat162*>(&a.out_hi[idx]) = oh;
                        *reinterpret_cast<__nv_bfloat162*>(&a.out_lo[idx]) = ol;
                    }
                }
            }
        }
    }
}

// ---------------- attention softmax + final ----------------
__global__ void att_kernel(const float* __restrict__ T1, const float* __restrict__ W2,
                           const float* __restrict__ b2, float* __restrict__ att) {
    int b = blockIdx.x, n = threadIdx.x;
    const float* t = T1 + ((size_t)b*NNODE + n)*DD;
    float s = b2[0];
    #pragma unroll 8
    for (int d = 0; d < DD; ++d) s += t[d] * W2[d];
    __shared__ float sv[NNODE];
    sv[n] = s;
    __syncthreads();
    float m = -1e30f;
    #pragma unroll 8
    for (int j = 0; j < NNODE; ++j) m = fmaxf(m, sv[j]);
    float e = expf(s - m);
    __shared__ float se[NNODE];
    se[n] = e;
    __syncthreads();
    float tot = 0.f;
    #pragma unroll 8
    for (int j = 0; j < NNODE; ++j) tot += se[j];
    att[b*NNODE + n] = e / tot;
}

__global__ void final_kernel(const float* __restrict__ att, const float* __restrict__ outbuf,
                             const float* __restrict__ resid, float* __restrict__ res) {
    int b = blockIdx.x, d = threadIdx.x;
    const float* a = att + b*NNODE;
    const float* o = outbuf + (size_t)b*NNODE*DD + d;
    float s = 0.f;
    #pragma unroll 8
    for (int n = 0; n < NNODE; ++n) s += a[n] * o[(size_t)n*DD];
    float v = tanhf(s) + resid[b*DD + d];
    res[b*DD + d] = fmaxf(v, 0.f);
}

// ---------------- launcher ----------------
extern "C" void kernel_launch(void* const* d_in, const int* in_sizes, int n_in,
                              void* d_out, int out_size) {
    const float* prop0  = (const float*)d_in[0];
    const float* edge0  = (const float*)d_in[1];
    const float* A      = (const float*)d_in[2];
    const float* W_link = (const float*)d_in[3];
    const float* b_link = (const float*)d_in[4];
    const float* W_r    = (const float*)d_in[5];
    const float* b_r    = (const float*)d_in[6];
    const float* W_z    = (const float*)d_in[7];
    const float* b_z    = (const float*)d_in[8];
    const float* W_h    = (const float*)d_in[9];
    const float* b_h    = (const float*)d_in[10];
    const float* W_att1 = (const float*)d_in[11];
    const float* b_att1 = (const float*)d_in[12];
    const float* W_att2 = (const float*)d_in[13];
    const float* b_att2 = (const float*)d_in[14];
    const float* W_out  = (const float*)d_in[15];
    const float* b_out  = (const float*)d_in[16];

    float* outp     = (float*)d_out;
    float* res_out  = outp;
    float* out_out  = outp + (size_t)BATCH*DD;
    float* edge_out = out_out + (size_t)BATCH*NNODE*DD;

    float *pM, *pMT, *pCv, *pZ, *pDv, *pRs, *pAtt, *pResid;
    __nv_bfloat16 *pPhi, *pPlo, *pph0, *ppl0, *pph1, *ppl1, *pRph, *pRpl;
    __nv_bfloat16 *pEhi, *pElo, *pAhi, *pAlo, *pGhi, *pGlo, *pWPhi, *pWPlo;
    __nv_bfloat16 *pWa1h, *pWa1l, *pWoh, *pWol, *pM5h, *pM5l;
    cudaGetSymbolAddress((void**)&pM, g_M);
    cudaGetSymbolAddress((void**)&pMT, g_MT);
    cudaGetSymbolAddress((void**)&pCv, g_cv);
    cudaGetSymbolAddress((void**)&pZ, g_Z);
    cudaGetSymbolAddress((void**)&pDv, g_dv);
    cudaGetSymbolAddress((void**)&pRs, g_rs);
    cudaGetSymbolAddress((void**)&pAtt, g_att);
    cudaGetSymbolAddress((void**)&pResid, g_resid);
    cudaGetSymbolAddress((void**)&pPhi, g_Phi);
    cudaGetSymbolAddress((void**)&pPlo, g_Plo);
    cudaGetSymbolAddress((void**)&pph0, g_ph0);
    cudaGetSymbolAddress((void**)&ppl0, g_pl0);
    cudaGetSymbolAddress((void**)&pph1, g_ph1);
    cudaGetSymbolAddress((void**)&ppl1, g_pl1);
    cudaGetSymbolAddress((void**)&pRph, g_rph);
    cudaGetSymbolAddress((void**)&pRpl, g_rpl);
    cudaGetSymbolAddress((void**)&pEhi, g_Ehi);
    cudaGetSymbolAddress((void**)&pElo, g_Elo);
    cudaGetSymbolAddress((void**)&pAhi, g_Ahi);
    cudaGetSymbolAddress((void**)&pAlo, g_Alo);
    cudaGetSymbolAddress((void**)&pGhi, g_Ghi);
    cudaGetSymbolAddress((void**)&pGlo, g_Glo);
    cudaGetSymbolAddress((void**)&pWPhi, g_WPhi);
    cudaGetSymbolAddress((void**)&pWPlo, g_WPlo);
    cudaGetSymbolAddress((void**)&pWa1h, g_Wa1hi);
    cudaGetSymbolAddress((void**)&pWa1l, g_Wa1lo);
    cudaGetSymbolAddress((void**)&pWoh, g_Wohi);
    cudaGetSymbolAddress((void**)&pWol, g_Wolo);
    cudaGetSymbolAddress((void**)&pM5h, g_M5hi);
    cudaGetSymbolAddress((void**)&pM5l, g_M5lo);

    // --- weight prep ---
    transpose_kernel<<<DD, DD>>>(W_link, pM, DD, 0);                    // M_1 = W^T [j][k]
    for (int k = 1; k < NSTEPS; ++k)
        matpow_kernel<<<DD, DD>>>(pM + (k-1)*T128, W_link, pM + k*T128);
    for (int s = 0; s < NSTEPS; ++s)
        transpose_kernel<<<DD, DD>>>(pM + s*T128, pMT + s*T128, DD, 0); // MT_s [k][j]
    cvec_init_kernel<<<1, DD>>>(b_link, pCv);
    for (int k = 1; k < NSTEPS; ++k)
        cvec_step_kernel<<<1, DD>>>(pCv + (k-1)*DD, W_link, b_link, pCv + k*DD);
    {
        dim3 gg(2, 15);
        prep_G_kernel<<<gg, 256>>>(W_r, W_z, W_h, pMT, pGhi, pGlo);
    }
    dvec_kernel<<<15, DD>>>(W_r, W_z, W_h, pCv, pDv);
    split_mat_kernel<<<DD, DD>>>(W_r, 2*DD, DD, pWPhi + 0*T128, pWPlo + 0*T128);
    split_mat_kernel<<<DD, DD>>>(W_z, 2*DD, DD, pWPhi + 1*T128, pWPlo + 1*T128);
    split_mat_kernel<<<DD, DD>>>(W_h, 2*DD, DD, pWPhi + 2*T128, pWPlo + 2*T128);
    split_mat_kernel<<<DD, DD>>>(W_att1, DD, 0, pWa1h, pWa1l);
    split_mat_kernel<<<DD, DD>>>(W_out, DD, 0, pWoh, pWol);
    split_mat_kernel<<<DD, DD>>>(pMT + 4*T128, DD, 0, pM5h, pM5l);      // M5B = MT_5

    // --- data conversions ---
    split_big_kernel<<<4096, 256>>>(edge0, pEhi, pElo, (long)NRE*DD/4);
    split_big_kernel<<<1024, 256>>>(prop0, pph0, ppl0, (long)NR*DD/4);
    split_big_kernel<<<2048, 256>>>(A, pAhi, pAlo, (long)BATCH*NNODE*NEDGE/4);

    // --- heavy one-time ---
    rowsum_kernel<<<NR, 128>>>(A, pRs);
    residual_kernel<<<BATCH, DD>>>(prop0, edge0, pResid);
    bmm_tc_kernel<<<BATCH, 256>>>(pAhi, pAlo, pEhi, pElo, pPhi, pPlo);  // P split-bf16

    // edge_out = edge0 @ M5 + c5 (tensor cores)
    {
        TCArgs a = {};
        a.xs[0] = pEhi; a.ws[0] = pM5h;
        a.xs[1] = pEhi; a.ws[1] = pM5l;
        a.xs[2] = pElo; a.ws[2] = pM5h;
        a.nterms = 3;
        a.bias = pCv + 4*DD;
        a.outf = edge_out;
        tc_gemm<4><<<NRE/128, 256>>>(a);
    }

    // --- 5 GRU steps ---
    __nv_bfloat16* ph[2] = {pph0, pph1};
    __nv_bfloat16* pl[2] = {ppl0, ppl1};
    int cur = 0;
    for (int s = 0; s < NSTEPS; ++s) {
        int cb = s * 3;
        // R: r*prop
        {
            TCArgs a = {};
            a.xs[0] = pPhi;    a.ws[0] = pGhi + (cb+0)*T128;
            a.xs[1] = pPhi;    a.ws[1] = pGlo + (cb+0)*T128;
            a.xs[2] = pPlo;    a.ws[2] = pGhi + (cb+0)*T128;
            a.xs[3] = ph[cur]; a.ws[3] = pWPhi + 0*T128;
            a.xs[4] = ph[cur]; a.ws[4] = pWPlo + 0*T128;
            a.xs[5] = pl[cur]; a.ws[5] = pWPhi + 0*T128;
            a.nterms = 6;
            a.bias = b_r; a.dvec = pDv + (cb+0)*DD; a.rs = pRs;
            a.p_hi = ph[cur]; a.p_lo = pl[cur];
            a.out_hi = pRph; a.out_lo = pRpl;
            tc_gemm<0><<<NR/128, 256>>>(a);
        }
        // Z
        {
            TCArgs a = {};
            a.xs[0] = pPhi;    a.ws[0] = pGhi + (cb+1)*T128;
            a.xs[1] = pPhi;    a.ws[1] = pGlo + (cb+1)*T128;
            a.xs[2] = pPlo;    a.ws[2] = pGhi + (cb+1)*T128;
            a.xs[3] = ph[cur]; a.ws[3] = pWPhi + 1*T128;
            a.xs[4] = ph[cur]; a.ws[4] = pWPlo + 1*T128;
            a.xs[5] = pl[cur]; a.ws[5] = pWPhi + 1*T128;
            a.nterms = 6;
            a.bias = b_z; a.dvec = pDv + (cb+1)*DD; a.rs = pRs;
            a.outf = pZ;
            tc_gemm<1><<<NR/128, 256>>>(a);
        }
        // H: prop update
        {
            TCArgs a = {};
            a.xs[0] = pPhi; a.ws[0] = pGhi + (cb+2)*T128;
            a.xs[1] = pPhi; a.ws[1] = pGlo + (cb+2)*T128;
            a.xs[2] = pPlo; a.ws[2] = pGhi + (cb+2)*T128;
            a.xs[3] = pRph; a.ws[3] = pWPhi + 2*T128;
            a.xs[4] = pRph; a.ws[4] = pWPlo + 2*T128;
            a.xs[5] = pRpl; a.ws[5] = pWPhi + 2*T128;
            a.nterms = 6;
            a.bias = b_h; a.dvec = pDv + (cb+2)*DD; a.rs = pRs;
            a.p_hi = ph[cur]; a.p_lo = pl[cur]; a.zbuf = pZ;
            a.out_hi = ph[cur^1]; a.out_lo = pl[cur^1];
            tc_gemm<2><<<NR/128, 256>>>(a);
        }
        cur ^= 1;
    }

    // --- readout ---
    {
        TCArgs a = {};
        a.xs[0] = ph[cur]; a.ws[0] = pWa1h;
        a.xs[1] = ph[cur]; a.ws[1] = pWa1l;
        a.xs[2] = pl[cur]; a.ws[2] = pWa1h;
        a.nterms = 3; a.bias = b_att1; a.outf = pZ;   // t1 -> g_Z
        tc_gemm<3><<<NR/128, 256>>>(a);
    }
    att_kernel<<<BATCH, NNODE>>>(pZ, W_att2, b_att2, pAtt);
    {
        TCArgs a = {};
        a.xs[0] = ph[cur]; a.ws[0] = pWoh;
        a.xs[1] = ph[cur]; a.ws[1] = pWol;
        a.xs[2] = pl[cur]; a.ws[2] = pWoh;
        a.nterms = 3; a.bias = b_out; a.outf = out_out;
        tc_gemm<3><<<NR/128, 256>>>(a);
    }
    final_kernel<<<BATCH, DD>>>(pAtt, out_out, pResid, res_out);
}